// round 8
// baseline (speedup 1.0000x reference)
#include <cuda_runtime.h>
#include <cstdint>
#include <cstddef>

// ---------------- problem constants ----------------
#define D_MODEL   1024
#define D_PROJ    256
#define MTILE     128                  // rows per CTA
#define NCHUNKS   32                   // K chunks of 32 fp32 (128B per row)
#define EPS1      1e-5f

// smem map (bytes):
//   [0, 4096)      suv: u[256] v[256] g2[256] b2[256]
//   [4096, 6144)   s1p[256] s2p[256]
//   [6144, 7168)   ca[128] cb[128]
//   [8192, ...)    3 stages: A 16KB + B 32KB each
//   epilogue reuses stage0: rowacc[128][4][2] (4KB), mu2[128], rs2[128]
#define SMEM_STAGE_OFF 8192
#define A_BYTES   16384                // 128 rows x 128B
#define B_BYTES   32768                // 256 rows x 128B
#define STAGE_BYTES 49152u
#define SMEM_BYTES (SMEM_STAGE_OFF + 3 * 49152)   // 155648

// ---------------- device scratch ----------------
// g_Wp layout: [p][kc*32 + s], slot s = 16h+4c+j holds k_local = 16h+c+4j.
__device__ float g_Wp[D_PROJ * D_MODEL];
__device__ float g_u[D_PROJ];
__device__ float g_v[D_PROJ];

// ---------------- helpers ----------------
static __device__ __forceinline__ uint32_t smem_u32(const void* p) {
    uint32_t a;
    asm("{ .reg .u64 t; cvta.to.shared.u64 t, %1; cvt.u32.u64 %0, t; }" : "=r"(a) : "l"(p));
    return a;
}

// conflict-free group swizzle: sigma(r) = ((r&1)<<2) | ((r>>1)&3)
static __device__ __forceinline__ uint32_t sig(int r) {
    return (((uint32_t)r & 1u) << 2) | (((uint32_t)r >> 1) & 3u);
}

#define CP_COMMIT() asm volatile("cp.async.commit_group;" ::: "memory")
#define CP_WAIT1()  asm volatile("cp.async.wait_group 1;" ::: "memory")
#define CP_WAIT0()  asm volatile("cp.async.wait_group 0;" ::: "memory")

static __device__ __forceinline__ uint32_t f2tf32(float f) {
    uint32_t u;
    asm("cvt.rna.tf32.f32 %0, %1;" : "=r"(u) : "f"(f));
    return u;
}

// raw fp32 bits fed to tf32 MMA (truncation round on A; B pre-rounded rna)
#define MMA_TF32(d, a0, a1, a2, a3, b0, b1)                                   \
    asm volatile("mma.sync.aligned.m16n8k8.row.col.f32.tf32.tf32.f32 "        \
        "{%0,%1,%2,%3}, {%4,%5,%6,%7}, {%8,%9}, {%0,%1,%2,%3};"               \
        : "+f"((d)[0]), "+f"((d)[1]), "+f"((d)[2]), "+f"((d)[3])              \
        : "r"(a0), "r"(a1), "r"(a2), "r"(a3), "r"(b0), "r"(b1))

#define LDS128F(v, addr)                                                      \
    asm volatile("ld.shared.v4.f32 {%0,%1,%2,%3}, [%4];"                      \
        : "=f"((v).x), "=f"((v).y), "=f"((v).z), "=f"((v).w) : "r"(addr))

#define LDS128U(v, addr)                                                      \
    asm volatile("ld.shared.v4.b32 {%0,%1,%2,%3}, [%4];"                      \
        : "=r"((v).x), "=r"((v).y), "=r"((v).z), "=r"((v).w) : "r"(addr))

// ---------------- prep: W' = g1.*W (tf32-rna), permuted layout; u, v ----------------
__global__ void __launch_bounds__(256) prep_kernel(
    const float* __restrict__ W, const float* __restrict__ g1,
    const float* __restrict__ b1, const float* __restrict__ bias)
{
    __shared__ float ru[8], rv[8];
    int p = blockIdx.x, t = threadIdx.x;
    const float* wrow = W + (size_t)p * D_MODEL;
    float u = 0.f, v = 0.f;
#pragma unroll
    for (int i = 0; i < 4; ++i) {
        int d = t + i * 256;
        float w  = wrow[d];
        float gw = g1[d] * w;
        u += gw;
        v += b1[d] * w;
        int kc = d >> 5, kk = d & 31;
        int h = kk >> 4, c = kk & 3, j = (kk >> 2) & 3;
        int s = (h << 4) | (c << 2) | j;
        g_Wp[(size_t)p * D_MODEL + kc * 32 + s] = __uint_as_float(f2tf32(gw));
    }
#pragma unroll
    for (int o = 16; o > 0; o >>= 1) {
        u += __shfl_xor_sync(0xFFFFFFFFu, u, o);
        v += __shfl_xor_sync(0xFFFFFFFFu, v, o);
    }
    if ((t & 31) == 0) { ru[t >> 5] = u; rv[t >> 5] = v; }
    __syncthreads();
    if (t == 0) {
        float uu = 0.f, vv = 0.f;
#pragma unroll
        for (int i = 0; i < 8; ++i) { uu += ru[i]; vv += rv[i]; }
        g_u[p] = uu;
        g_v[p] = vv + bias[p];
    }
}

// ---------------- main fused kernel ----------------
__global__ void __launch_bounds__(256, 1) fused_kernel(
    const float* __restrict__ x,
    const float* __restrict__ g2v, const float* __restrict__ b2v,
    float* __restrict__ out)
{
    extern __shared__ char smem[];
    const uint32_t sb = smem_u32(smem);
    const int tid  = threadIdx.x;
    const int lane = tid & 31;
    const int wid  = tid >> 5;
    const int wm   = wid >> 2;          // 0..1
    const int wn   = wid & 3;           // 0..3
    const int qt   = lane & 3;
    const int qr   = lane >> 2;

    float* suv = (float*)smem;          // u, v, g2, b2
    suv[tid]       = g_u[tid];
    suv[256 + tid] = g_v[tid];
    suv[512 + tid] = g2v[tid];
    suv[768 + tid] = b2v[tid];

    const size_t row0 = (size_t)blockIdx.x * MTILE;

    // ---- A loader consts: thread covers rows r = 8i + wid, element kk = tid&31 ----
    const int akk = tid & 31;
    const int ahh = akk >> 4, acc_ = akk & 3, ajj = (akk >> 2) & 3;
    const uint32_t aGlog = (uint32_t)(4 * ahh + acc_);
    const uint32_t a_dst = sb + SMEM_STAGE_OFF + (uint32_t)wid * 128
                         + (((aGlog ^ sig(wid)) << 4)) + (uint32_t)ajj * 4;
    const char* a_src = (const char*)x + (row0 + (size_t)wid) * 4096 + (size_t)akk * 4;

    // ---- B loader consts: thread covers rows p = 32i + tp, group bq = tid&7 ----
    const int tp = tid >> 3, bq = tid & 7;
    const uint32_t b_dst = sb + SMEM_STAGE_OFF + A_BYTES + (uint32_t)tp * 128
                         + ((((uint32_t)bq ^ sig(tp)) << 4));
    const char* b_src = (const char*)g_Wp + (size_t)tp * 4096 + (size_t)bq * 16;

    // ---- fragment bases, both halves precomputed (h enters via XOR 64) ----
    const uint32_t qoff = (((uint32_t)qt ^ sig(qr)) << 4);
    const uint32_t aRow = sb + SMEM_STAGE_OFF + (uint32_t)(wm * 64 + qr) * 128;
    const uint32_t bRow = sb + SMEM_STAGE_OFF + A_BYTES + (uint32_t)(wn * 64 + qr) * 128;
    const uint32_t aF0 = aRow + qoff;
    const uint32_t aF1 = aRow + (qoff ^ 64u);
    const uint32_t bF0 = bRow + qoff;
    const uint32_t bF1 = bRow + (qoff ^ 64u);

    // ---- LN1 stat consts ----
    const int srow = tid & 127, shh = tid >> 7;
    const uint32_t sBase = sb + SMEM_STAGE_OFF + (uint32_t)srow * 128;
    const uint32_t ssig = sig(srow);
    uint32_t sOff[4];
#pragma unroll
    for (int i = 0; i < 4; ++i)
        sOff[i] = (((uint32_t)(shh * 4 + i) ^ ssig) << 4);

    float acc[4][8][4];
#pragma unroll
    for (int a = 0; a < 4; ++a)
#pragma unroll
        for (int b = 0; b < 8; ++b)
#pragma unroll
            for (int c = 0; c < 4; ++c) acc[a][b][c] = 0.f;

    float s1 = 0.f, s2 = 0.f;

// KOFF: compile-time byte offset of the chunk along K; SOFF: compile-time stage offset
#define LOADC(KOFF, SOFF)                                                      \
    do {                                                                       \
        const char* _a = a_src + (KOFF);                                       \
        _Pragma("unroll")                                                      \
        for (int i = 0; i < 16; ++i)                                           \
            asm volatile("cp.async.ca.shared.global [%0], [%1], 4;"            \
                :: "r"(a_dst + (SOFF) + (uint32_t)i * 1024),                   \
                   "l"(_a + (size_t)i * 32768));                               \
        const char* _b = b_src + (KOFF);                                       \
        _Pragma("unroll")                                                      \
        for (int i = 0; i < 8; ++i)                                            \
            asm volatile("cp.async.cg.shared.global [%0], [%1], 16;"           \
                :: "r"(b_dst + (SOFF) + (uint32_t)i * 4096),                   \
                   "l"(_b + (size_t)i * 131072));                              \
    } while (0)

#define STATS(SOFF)                                                            \
    do {                                                                       \
        _Pragma("unroll")                                                      \
        for (int i = 0; i < 4; ++i) {                                          \
            float4 vv;                                                         \
            LDS128F(vv, sBase + (SOFF) + sOff[i]);                             \
            s1 += (vv.x + vv.y) + (vv.z + vv.w);                               \
            s2 += (vv.x * vv.x + vv.y * vv.y) + (vv.z * vv.z + vv.w * vv.w);   \
        }                                                                      \
    } while (0)

#define COMPUTE(SOFF)                                                          \
    do {                                                                       \
        _Pragma("unroll")                                                      \
        for (int h = 0; h < 2; ++h) {                                          \
            const uint32_t _af = (h ? aF1 : aF0) + (SOFF);                     \
            const uint32_t _bf = (h ? bF1 : bF0) + (SOFF);                     \
            uint4 bb[8];                                                       \
            _Pragma("unroll")                                                  \
            for (int nt = 0; nt < 8; ++nt)                                     \
                LDS128U(bb[nt], _bf + (uint32_t)nt * 1024);                    \
            _Pragma("unroll")                                                  \
            for (int mt = 0; mt < 4; ++mt) {                                   \
                uint4 alo, ahi;                                                \
                LDS128U(alo, _af + (uint32_t)mt * 2048);                       \
                LDS128U(ahi, _af + (uint32_t)mt * 2048 + 1024);                \
                _Pragma("unroll")                                              \
                for (int nt = 0; nt < 8; ++nt) {                               \
                    MMA_TF32(acc[mt][nt], alo.x, ahi.x, alo.y, ahi.y,          \
                             bb[nt].x, bb[nt].y);                              \
                    MMA_TF32(acc[mt][nt], alo.z, ahi.z, alo.w, ahi.w,          \
                             bb[nt].z, bb[nt].w);                              \
                }                                                              \
            }                                                                  \
        }                                                                      \
    } while (0)

// one chunk: wait, sync, prefetch chunk+2 (compile-time stage), compute
#define ITER(KOFF2, SCUR, SNXT)                                                \
    do {                                                                       \
        CP_WAIT1();                                                            \
        __syncthreads();                                                       \
        LOADC((KOFF2), (SNXT));                                                \
        CP_COMMIT();                                                           \
        STATS((SCUR));                                                         \
        COMPUTE((SCUR));                                                       \
    } while (0)

    // ---------------- mainloop: 3-stage rotation, fully immediate addresses ----------------
    LOADC(0u, 0u); CP_COMMIT();
    LOADC(128u, STAGE_BYTES); CP_COMMIT();

#pragma unroll 1
    for (int kcb = 0; kcb < 30; kcb += 3) {
        const size_t kbase = (size_t)kcb * 128;
        ITER(kbase + 256, 0u,               2u * STAGE_BYTES);
        ITER(kbase + 384, STAGE_BYTES,      0u);
        ITER(kbase + 512, 2u * STAGE_BYTES, STAGE_BYTES);
        a_src += 384; b_src += 384;        // fold K advance into two pointer bumps
        // note: KOFF arguments above are relative to the *original* pointers;
        // compensate by subtracting the accumulated advance
        a_src -= 384; b_src -= 384;
    }
    // chunks 30 (stage 0) and 31 (stage 1), no more loads
    CP_WAIT1();
    __syncthreads();
    STATS(0u);
    COMPUTE(0u);
    CP_WAIT0();
    __syncthreads();
    STATS(STAGE_BYTES);
    COMPUTE(STAGE_BYTES);

    // ---------------- LN1 finalize ----------------
    float* s1p = (float*)(smem + 4096);
    float* s2p = s1p + 256;
    float* ca = (float*)(smem + 6144);
    float* cb = ca + 128;
    float* rowacc = (float*)(smem + SMEM_STAGE_OFF);        // [128][4][2]
    float* mu2a = (float*)(smem + SMEM_STAGE_OFF + 4096);
    float* rs2a = mu2a + 128;

    s1p[tid] = s1; s2p[tid] = s2;
    __syncthreads();

    if (tid < 128) {
        float a = s1p[tid] + s1p[tid + 128];
        float b = s2p[tid] + s2p[tid + 128];
        float mu  = a * (1.0f / (float)D_MODEL);
        float var = fmaf(-mu, mu, b * (1.0f / (float)D_MODEL));
        float rs  = rsqrtf(var + EPS1);
        ca[tid] = rs;
        cb[tid] = -mu * rs;
    }
    rowacc[tid] = 0.f; rowacc[tid + 256] = 0.f;
    rowacc[tid + 512] = 0.f; rowacc[tid + 768] = 0.f;
    __syncthreads();

    // ---------------- h = ca*acc + cb*u + v; LN2 partial sums ----------------
#pragma unroll
    for (int mt = 0; mt < 4; ++mt) {
#pragma unroll
        for (int b = 0; b < 2; ++b) {
            int rr = wm * 64 + mt * 16 + qr + 8 * b;
            float cav = ca[rr], cbv = cb[rr];
            float t1 = 0.f, t2 = 0.f;
#pragma unroll
            for (int nt = 0; nt < 8; ++nt) {
                int p0 = wn * 64 + nt * 8 + 2 * qt;
                float h0 = fmaf(cav, acc[mt][nt][2 * b],     fmaf(cbv, suv[p0],     suv[256 + p0]));
                float h1 = fmaf(cav, acc[mt][nt][2 * b + 1], fmaf(cbv, suv[p0 + 1], suv[256 + p0 + 1]));
                acc[mt][nt][2 * b]     = h0;
                acc[mt][nt][2 * b + 1] = h1;
                t1 += h0 + h1;
                t2 += h0 * h0 + h1 * h1;
            }
            t1 += __shfl_xor_sync(0xFFFFFFFFu, t1, 1);
            t2 += __shfl_xor_sync(0xFFFFFFFFu, t2, 1);
            t1 += __shfl_xor_sync(0xFFFFFFFFu, t1, 2);
            t2 += __shfl_xor_sync(0xFFFFFFFFu, t2, 2);
            if (qt == 0) {
                rowacc[(rr * 4 + wn) * 2]     = t1;
                rowacc[(rr * 4 + wn) * 2 + 1] = t2;
            }
        }
    }
    __syncthreads();

    if (tid < 128) {
        float t1 = 0.f, t2 = 0.f;
#pragma unroll
        for (int w = 0; w < 4; ++w) {
            t1 += rowacc[(tid * 4 + w) * 2];
            t2 += rowacc[(tid * 4 + w) * 2 + 1];
        }
        float mu  = t1 * (1.0f / (float)D_PROJ);
        float var = fmaf(-mu, mu, t2 * (1.0f / (float)D_PROJ));
        mu2a[tid] = mu;
        rs2a[tid] = rsqrtf(var + EPS1);
    }
    __syncthreads();

    // ---------------- normalize + store ----------------
    float* outp = out + row0 * D_PROJ;
#pragma unroll
    for (int mt = 0; mt < 4; ++mt) {
#pragma unroll
        for (int b = 0; b < 2; ++b) {
            int rr = wm * 64 + mt * 16 + qr + 8 * b;
            float mu = mu2a[rr], rs = rs2a[rr];
#pragma unroll
            for (int nt = 0; nt < 8; ++nt) {
                int p0 = wn * 64 + nt * 8 + 2 * qt;
                float o0 = fmaf((acc[mt][nt][2 * b]     - mu) * rs, suv[512 + p0],     suv[768 + p0]);
                float o1 = fmaf((acc[mt][nt][2 * b + 1] - mu) * rs, suv[512 + p0 + 1], suv[768 + p0 + 1]);
                float2 o = make_float2(o0, o1);
                *(float2*)(outp + (size_t)rr * D_PROJ + p0) = o;
            }
        }
    }
#undef LOADC
#undef STATS
#undef COMPUTE
#undef ITER
}

// ---------------- launch ----------------
extern "C" void kernel_launch(void* const* d_in, const int* in_sizes, int n_in,
                              void* d_out, int out_size)
{
    const float* x    = (const float*)d_in[0];
    const float* g1   = (const float*)d_in[1];
    const float* b1   = (const float*)d_in[2];
    const float* W    = (const float*)d_in[3];
    const float* bias = (const float*)d_in[4];
    const float* g2   = (const float*)d_in[5];
    const float* b2   = (const float*)d_in[6];
    float* out = (float*)d_out;

    int n_tok = in_sizes[0] / D_MODEL;          // 65536
    int grid  = n_tok / MTILE;                  // 512

    prep_kernel<<<D_PROJ, 256>>>(W, g1, b1, bias);

    cudaFuncSetAttribute(fused_kernel, cudaFuncAttributeMaxDynamicSharedMemorySize, SMEM_BYTES);
    fused_kernel<<<grid, 256, SMEM_BYTES>>>(x, g2, b2, out);
}